// round 17
// baseline (speedup 1.0000x reference)
#include <cuda_runtime.h>
#include <cstdint>

// out[b,c,h,w] = (1/256) * sum_{p,o in 0..8} inp[b, p*9+o, h, w] * sec[b, c, h+p-4, w+o-4]
// mma.sync m16n8k8 tf32. prep builds banded-B fragments in gmem scratch;
// main: CTA = 32ch x 16px x 64 h-rows, NT=128, smem = A-ring only (30KB, 5 CTAs/SM).
// B fragments load straight from scratch into registers (no smem round trip).

#define HH 128
#define WW 128
#define CC 256
#define MD 4
#define HW (HH*WW)

#define NT 128
#define MCH 32
#define HSEG 64
#define NFRAG 576                 // 9p x 2nt x 32 lanes
#define RSLOT (2*3*512)           // 3072
#define SMEM_BYTES (10*RSLOT)     // 30720: A ring only

__device__ uint4 g_bfrag[(size_t)8 * 8 * 128 * NFRAG];   // [b][wt][h][idx] 75.5MB

static __device__ __forceinline__ uint32_t f2tf(float f) {
    uint32_t r; asm("cvt.rna.tf32.f32 %0, %1;" : "=r"(r) : "f"(f)); return r;
}

static __device__ __forceinline__ void mma8(float* d, const uint4& a, uint32_t b0, uint32_t b1) {
    asm volatile("mma.sync.aligned.m16n8k8.row.col.f32.tf32.tf32.f32 "
                 "{%0,%1,%2,%3}, {%4,%5,%6,%7}, {%8,%9}, {%0,%1,%2,%3};"
                 : "+f"(d[0]), "+f"(d[1]), "+f"(d[2]), "+f"(d[3])
                 : "r"(a.x), "r"(a.y), "r"(a.z), "r"(a.w), "r"(b0), "r"(b1));
}

// ---- prep: one thread = one B fragment (p, nt, lane) for one (b, wt, h) ----
__global__ void __launch_bounds__(NFRAG)
prep_b_kernel(const float* __restrict__ inp)
{
    const int idx = threadIdx.x;          // 0..575
    const int wt  = blockIdx.x;
    const int h   = blockIdx.y;
    const int b   = blockIdx.z;
    const int w0  = wt * 16;

    const int l  = idx & 31;
    const int nt = (idx >> 5) & 1;
    const int p  = idx >> 6;
    const int x  = 8 * nt + (l >> 2);
    const int o0 = (l & 3) - (l >> 2);

    const float* ib = inp + ((size_t)(b * 81 + p * 9) * HH + h) * WW + (w0 + x)
                          + (ptrdiff_t)o0 * HW;
    float g0 = ((unsigned)(o0)      <= 8u) ? __ldg(ib)           : 0.f;
    float g1 = ((unsigned)(o0 + 4)  <= 8u) ? __ldg(ib + 4 * HW)  : 0.f;
    float g2 = ((unsigned)(o0 + 8)  <= 8u) ? __ldg(ib + 8 * HW)  : 0.f;
    float g3 = ((unsigned)(o0 + 12) <= 8u) ? __ldg(ib + 12 * HW) : 0.f;

    g_bfrag[(((size_t)b * 8 + wt) * 128 + h) * NFRAG + idx] =
        make_uint4(f2tf(g0), f2tf(g1), f2tf(g2), f2tf(g3));
}

__global__ void __launch_bounds__(NT, 5)
corr_mma_kernel(const float* __restrict__ inp,
                const float* __restrict__ sec,
                float* __restrict__ out)
{
    extern __shared__ char smem[];
    const int tid  = threadIdx.x;
    const int wid  = tid >> 5;
    const int lane = tid & 31;
    const int w0   = blockIdx.x * 16;
    const int c0   = blockIdx.y * MCH;
    const int b    = blockIdx.z >> 1;
    const int h0   = (blockIdx.z & 1) * HSEG;

    const int cbw = wid & 1;      // warp's channel block (16 ch)
    const int ntw = wid >> 1;     // warp's n-tile (8 px)

    // ---- hoisted ldA/stA descriptors (2 slots) ----
    bool aact[2], am0[2], am1[2];
    const float* aptr[2];
    int asmo[2];
    #pragma unroll
    for (int i = 0; i < 2; i++) {
        int idx = tid + i * NT;
        aact[i] = idx < 192;
        int l  = idx & 31;
        int s  = (idx >> 5) % 3;
        int cb = (idx / 96) & 1;
        int ch = cb * 16 + (l >> 2);
        int px = w0 - 4 + s * 8 + (l & 3);
        am0[i] = aact[i] && ((unsigned)px < WW);
        am1[i] = aact[i] && ((unsigned)(px + 4) < WW);
        aptr[i] = sec + ((size_t)(b * CC + c0 + ch) * HH) * WW + px;   // px signed
        asmo[i] = (cb * 3 + s) * 512 + l * 16;
    }

    // per-warp B fragment source (lane-matched, coalesced 512B per p)
    const uint4* bsrc = g_bfrag + (((size_t)b * 8 + blockIdx.x) * 128) * NFRAG
                      + ntw * 32 + lane;

    float4 pA[2];

    auto ldA = [&](int r) {
        #pragma unroll
        for (int i = 0; i < 2; i++) {
            const float* q = aptr[i] + (r << 7);
            float f0 = am0[i] ? __ldg(q)              : 0.f;
            float f1 = am0[i] ? __ldg(q + 8 * HW)     : 0.f;
            float f2 = am1[i] ? __ldg(q + 4)          : 0.f;
            float f3 = am1[i] ? __ldg(q + 8 * HW + 4) : 0.f;
            pA[i] = make_float4(f0, f1, f2, f3);
        }
    };
    auto stA = [&](int slot) {
        #pragma unroll
        for (int i = 0; i < 2; i++) {
            if (aact[i]) {
                uint4 v = make_uint4(f2tf(pA[i].x), f2tf(pA[i].y), f2tf(pA[i].z), f2tf(pA[i].w));
                *(uint4*)(smem + slot * RSLOT + asmo[i]) = v;
            }
        }
    };

    // ---- prologue: stage rows max(0,h0-4) .. h0+4, prefetch h0+5 ----
    {
        int rlo = h0 - MD; if (rlo < 0) rlo = 0;
        for (int r = rlo; r <= h0 + MD; r++) { ldA(r); stA(r % 10); }
        ldA(h0 + 5);
    }
    __syncthreads();

    const unsigned aoff_warp = (unsigned)(cbw * 3 * 512 + lane * 16);
    const float sc = 1.0f / (float)CC;

    int slot_st = (h0 + 5) % 10;      // ring slot receiving row h+5
    int s0 = (h0 + 6) % 10;           // ring slot of row h-4
    float* ob = out + ((size_t)(b * CC + c0 + cbw * 16 + (lane >> 2)) * HH + h0) * WW
                    + w0 + ntw * 8 + 2 * (lane & 3);

    #pragma unroll 1
    for (int h = h0; h < h0 + HSEG; h++) {
        // step 1: publish pending A staging (row h+5)
        if (h + 5 < HH) { stA(slot_st); slot_st = (slot_st == 9) ? 0 : slot_st + 1; }

        // step 2: prefetch next pending
        if (h + 6 < HH) ldA(h + 6);

        // step 3: compute (B straight from scratch; A from ring)
        float accE[4] = {0.f, 0.f, 0.f, 0.f};
        float accO[4] = {0.f, 0.f, 0.f, 0.f};
        const uint4* bh = bsrc + (size_t)h * NFRAG;
        if (h >= MD && h < HH - MD) {
            int sl = s0;
            #pragma unroll
            for (int p = 0; p < 9; p++) {
                const char* ab = smem + sl * RSLOT + aoff_warp;
                uint4 A0 = *(const uint4*)(ab + ntw * 512);
                uint4 A1 = *(const uint4*)(ab + (ntw + 1) * 512);
                uint4 B0 = __ldg(bh + p * 64);
                float* acc = (p & 1) ? accO : accE;
                mma8(acc, A0, B0.x, B0.y);
                mma8(acc, A1, B0.z, B0.w);
                sl = (sl == 9) ? 0 : sl + 1;
            }
        } else {
            int sl = s0;
            #pragma unroll
            for (int p = 0; p < 9; p++) {
                int r = h + p - MD;
                if ((unsigned)r < (unsigned)HH) {
                    const char* ab = smem + sl * RSLOT + aoff_warp;
                    uint4 A0 = *(const uint4*)(ab + ntw * 512);
                    uint4 A1 = *(const uint4*)(ab + (ntw + 1) * 512);
                    uint4 B0 = __ldg(bh + p * 64);
                    float* acc = (p & 1) ? accO : accE;
                    mma8(acc, A0, B0.x, B0.y);
                    mma8(acc, A1, B0.z, B0.w);
                }
                sl = (sl == 9) ? 0 : sl + 1;
            }
        }
        s0 = (s0 == 9) ? 0 : s0 + 1;

        // step 4: epilogue
        *(float2*)(ob)          = make_float2((accE[0] + accO[0]) * sc, (accE[1] + accO[1]) * sc);
        *(float2*)(ob + 8 * HW) = make_float2((accE[2] + accO[2]) * sc, (accE[3] + accO[3]) * sc);
        ob += WW;

        // step 5: barrier (A-ring visibility)
        __syncthreads();
    }
}

extern "C" void kernel_launch(void* const* d_in, const int* in_sizes, int n_in,
                              void* d_out, int out_size)
{
    const float* inp = (const float*)d_in[0];   // [B, 81, 128, 128]
    const float* sec = (const float*)d_in[1];   // [B, 256, 128, 128]
    float* out = (float*)d_out;                 // [B, 256, 128, 128]

    const int B = in_sizes[0] / (81 * HH * WW);

    cudaFuncSetAttribute(corr_mma_kernel,
                         cudaFuncAttributeMaxDynamicSharedMemorySize, SMEM_BYTES);

    dim3 pgrid(WW / 16, HH, B);                 // (8, 128, 8)
    prep_b_kernel<<<pgrid, NFRAG>>>(inp);

    dim3 grid(WW / 16, CC / MCH, B * 2);        // (8, 8, 16) = 1024 CTAs
    corr_mma_kernel<<<grid, NT, SMEM_BYTES>>>(inp, sec, out);
}